// round 1
// baseline (speedup 1.0000x reference)
#include <cuda_runtime.h>

#define MM 2
#define LL 6
#define NN 512
#define HH 64
#define VK 1.0f
#define SIG2 0.01f     // SIGMA^2
#define DDIM 2.0       // d

typedef unsigned long long u64;

// one partial per block, fixed-order reduction -> deterministic
__device__ double g_parts[MM * LL * NN];

__device__ __forceinline__ u64 pack2(float x) {
    u64 r; asm("mov.b64 %0, {%1,%1};" : "=l"(r) : "f"(x)); return r;
}
__device__ __forceinline__ u64 pack2f(float lo, float hi) {
    u64 r; asm("mov.b64 %0, {%1,%2};" : "=l"(r) : "f"(lo), "f"(hi)); return r;
}
__device__ __forceinline__ void unpack2(u64 v, float& lo, float& hi) {
    asm("mov.b64 {%0,%1}, %2;" : "=f"(lo), "=f"(hi) : "l"(v));
}
__device__ __forceinline__ u64 fma2(u64 a, u64 b, u64 c) {
    u64 d; asm("fma.rn.f32x2 %0, %1, %2, %3;" : "=l"(d) : "l"(a), "l"(b), "l"(c)); return d;
}

// Per-pair MLP: phi(r) and (optionally) dphi, d2phi.
// h1 = tanh(r*w1+b1); z2 = h1@W2 + b2; h2 = tanh(z2); phi = h2.w3 (+b3 added by caller)
// h1'  = (1-h1^2) w1
// h1'' = -2 h1 h1' w1
// h2'  = (1-h2^2) z2' ;  h2'' = (1-h2^2) z2'' - 2 h2 h2' z2'
template <bool DERIV>
__device__ __forceinline__ void mlp_pair(
    float r,
    const float* __restrict__ sW2, const float* __restrict__ sw1,
    const float* __restrict__ sb1, const float* __restrict__ sb2,
    const float* __restrict__ sw3, float* __restrict__ myh1,
    float& phi, float& dphi, float& d2phi)
{
    #pragma unroll 8
    for (int k = 0; k < HH; k++)
        myh1[k * 256] = tanhf(fmaf(r, sw1[k], sb1[k]));

    phi = 0.f; dphi = 0.f; d2phi = 0.f;

    for (int c = 0; c < HH; c += 16) {
        u64 z2[8], zp[8], zpp[8];
        #pragma unroll
        for (int p = 0; p < 8; p++) {
            z2[p]  = pack2f(sb2[c + 2 * p], sb2[c + 2 * p + 1]);
            zp[p]  = 0ull;
            zpp[p] = 0ull;
        }
        #pragma unroll 4
        for (int k = 0; k < HH; k++) {
            float h  = myh1[k * 256];
            u64 hh   = pack2(h);
            u64 hpx  = 0ull, hppx = 0ull;
            if (DERIV) {
                float w1k = sw1[k];
                float s   = fmaf(-h, h, 1.f);
                float hp  = s * w1k;
                float hpp = -2.f * h * hp * w1k;
                hpx  = pack2(hp);
                hppx = pack2(hpp);
            }
            const ulonglong2* wr = (const ulonglong2*)(sW2 + k * HH + c);
            #pragma unroll
            for (int q = 0; q < 4; q++) {
                ulonglong2 w = wr[q];
                z2[2 * q]     = fma2(w.x, hh, z2[2 * q]);
                z2[2 * q + 1] = fma2(w.y, hh, z2[2 * q + 1]);
                if (DERIV) {
                    zp[2 * q]      = fma2(w.x, hpx,  zp[2 * q]);
                    zp[2 * q + 1]  = fma2(w.y, hpx,  zp[2 * q + 1]);
                    zpp[2 * q]     = fma2(w.x, hppx, zpp[2 * q]);
                    zpp[2 * q + 1] = fma2(w.y, hppx, zpp[2 * q + 1]);
                }
            }
        }
        #pragma unroll
        for (int p = 0; p < 8; p++) {
            float a0, a1, p0 = 0.f, p1 = 0.f, q0 = 0.f, q1 = 0.f;
            unpack2(z2[p], a0, a1);
            if (DERIV) { unpack2(zp[p], p0, p1); unpack2(zpp[p], q0, q1); }
            float w30 = sw3[c + 2 * p], w31 = sw3[c + 2 * p + 1];

            float h2 = tanhf(a0);
            phi = fmaf(w30, h2, phi);
            if (DERIV) {
                float e   = fmaf(-h2, h2, 1.f);
                float hp2 = e * p0;
                float hq2 = fmaf(e, q0, -2.f * h2 * hp2 * p0);
                dphi  = fmaf(w30, hp2, dphi);
                d2phi = fmaf(w30, hq2, d2phi);
            }
            h2 = tanhf(a1);
            phi = fmaf(w31, h2, phi);
            if (DERIV) {
                float e   = fmaf(-h2, h2, 1.f);
                float hp2 = e * p1;
                float hq2 = fmaf(e, q1, -2.f * h2 * hp2 * p1);
                dphi  = fmaf(w31, hp2, dphi);
                d2phi = fmaf(w31, hq2, d2phi);
            }
        }
    }
}

__global__ void __launch_bounds__(256)
phi_loss_main(const float* __restrict__ data, const float* __restrict__ t,
              const float* __restrict__ w1, const float* __restrict__ b1,
              const float* __restrict__ W2, const float* __restrict__ b2,
              const float* __restrict__ w3, const float* __restrict__ b3p)
{
    extern __shared__ float sh[];
    float* sW2 = sh;                 // HH*HH
    float* sw1 = sW2 + HH * HH;      // HH
    float* sb1 = sw1 + HH;
    float* sb2 = sb1 + HH;
    float* sw3 = sb2 + HH;
    float* h1s = sw3 + HH;           // HH * 256, layout [k][tid]
    __shared__ float4 red[256];

    int tid = threadIdx.x;
    for (int idx = tid; idx < HH * HH; idx += 256) sW2[idx] = W2[idx];
    if (tid < HH) { sw1[tid] = w1[tid]; sb1[tid] = b1[tid]; sb2[tid] = b2[tid]; sw3[tid] = w3[tid]; }
    __syncthreads();

    int b = blockIdx.x;
    int i = b % NN;
    int l = (b / NN) % LL;
    int m = b / (NN * LL);
    bool deriv = (l < LL - 1);

    const float* snap = data + ((size_t)(m * LL + l)) * NN * 2;
    float xi0 = snap[i * 2 + 0];
    float xi1 = snap[i * 2 + 1];
    float b3  = b3p[0];

    float gx = 0.f, gy = 0.f, lap = 0.f, phis = 0.f;
    float* myh1 = h1s + tid;

    #pragma unroll
    for (int jj = 0; jj < 2; jj++) {
        int j = tid + jj * 256;
        float xj0 = snap[j * 2 + 0];
        float xj1 = snap[j * 2 + 1];
        float dx = xi0 - xj0, dy = xi1 - xj1;
        float ssq = dx * dx + dy * dy;
        bool active = (j != i);
        float r = (ssq > 0.f) ? sqrtf(ssq) : 0.f;

        float phi, dphi, d2phi;
        if (deriv) mlp_pair<true >(r, sW2, sw1, sb1, sb2, sw3, myh1, phi, dphi, d2phi);
        else       mlp_pair<false>(r, sW2, sw1, sb1, sb2, sw3, myh1, phi, dphi, d2phi);

        if (active) {
            phis += phi + b3;
            if (deriv) {
                lap += d2phi;
                float inv = 1.f / fmaxf(r, 1e-10f);
                gx = fmaf(dphi * inv, dx, gx);
                gy = fmaf(dphi * inv, dy, gy);
            }
        }
    }

    red[tid] = make_float4(gx, gy, lap, phis);
    __syncthreads();
    for (int s = 128; s > 0; s >>= 1) {
        if (tid < s) {
            float4 a = red[tid], c = red[tid + s];
            red[tid] = make_float4(a.x + c.x, a.y + c.y, a.z + c.z, a.w + c.w);
        }
        __syncthreads();
    }

    if (tid == 0) {
        float4 tot = red[0];
        double contrib = 0.0;
        if (deriv) {
            float dtl = t[l + 1] - t[l];
            float dgx = fmaf(-VK, xi0, -tot.x / NN);   // drift_x
            float dgy = fmaf(-VK, xi1, -tot.y / NN);   // drift_y
            contrib += (double)dtl * ((double)dgx * dgx + (double)dgy * dgy) / NN;          // diss
            contrib += (double)SIG2 * (double)dtl * ((double)tot.z / NN) / NN;              // diff (lap part)
        }
        if (l == 0 || l == LL - 1) {
            double sign = (l == 0) ? 2.0 : -2.0;   // -2*(E_last - E_first)
            contrib += sign * ((double)tot.w / ((double)NN * NN)
                             + 0.5 * (double)VK * ((double)xi0 * xi0 + (double)xi1 * xi1) / NN);
        }
        g_parts[b] = contrib;
    }
}

__global__ void __launch_bounds__(256)
phi_loss_finalize(const float* __restrict__ t, float* __restrict__ out)
{
    __shared__ double red[256];
    int tid = threadIdx.x;
    double s = 0.0;
    for (int idx = tid; idx < MM * LL * NN; idx += 256) s += g_parts[idx];
    red[tid] = s;
    __syncthreads();
    for (int k = 128; k > 0; k >>= 1) {
        if (tid < k) red[tid] += red[tid + k];
        __syncthreads();
    }
    if (tid == 0) {
        double S = red[0];
        // constant diffusion term: sum over m,l of SIG2*dt*VK*d  (dt telescopes)
        S += (double)MM * (double)SIG2 * (double)VK * DDIM * (double)(t[LL - 1] - t[0]);
        double res = S / (double)(MM * (LL - 1));
        out[0] = (float)(res * res);
    }
}

extern "C" void kernel_launch(void* const* d_in, const int* in_sizes, int n_in,
                              void* d_out, int out_size)
{
    const float* data = (const float*)d_in[0];
    const float* t    = (const float*)d_in[1];
    const float* w1   = (const float*)d_in[2];
    const float* b1   = (const float*)d_in[3];
    const float* W2   = (const float*)d_in[4];
    const float* b2   = (const float*)d_in[5];
    const float* w3   = (const float*)d_in[6];
    const float* b3   = (const float*)d_in[7];

    size_t smem = (size_t)(HH * HH + 4 * HH + HH * 256) * sizeof(float);  // 82944 B
    cudaFuncSetAttribute(phi_loss_main, cudaFuncAttributeMaxDynamicSharedMemorySize, (int)smem);

    phi_loss_main<<<MM * LL * NN, 256, smem>>>(data, t, w1, b1, W2, b2, w3, b3);
    phi_loss_finalize<<<1, 256>>>(t, (float*)d_out);
}

// round 2
// speedup vs baseline: 1.8064x; 1.8064x over previous
#include <cuda_runtime.h>

#define MM 2
#define LL 6
#define NN 512
#define HH 64
#define VK 1.0f
#define SIG2 0.01
#define DDIM 2.0
#define NPAIR 130816          // 512*511/2 = 511*256
#define PBLK 511              // pair-blocks per snapshot

typedef unsigned long long u64;

// per-block scalar partials (deterministic reduction in finalize)
__device__ double g_lap[12 * PBLK];
__device__ double g_phi[12 * PBLK];
// gradient accumulator, double atomics (order-independent to ~1e-16)
__device__ double g_vec[MM * LL * NN * 2];

__device__ __forceinline__ u64 pack2(float x) {
    u64 r; asm("mov.b64 %0, {%1,%1};" : "=l"(r) : "f"(x)); return r;
}
__device__ __forceinline__ u64 pack2f(float lo, float hi) {
    u64 r; asm("mov.b64 %0, {%1,%2};" : "=l"(r) : "f"(lo), "f"(hi)); return r;
}
__device__ __forceinline__ void unpack2(u64 v, float& lo, float& hi) {
    asm("mov.b64 {%0,%1}, %2;" : "=f"(lo), "=f"(hi) : "l"(v));
}
__device__ __forceinline__ u64 fma2(u64 a, u64 b, u64 c) {
    u64 d; asm("fma.rn.f32x2 %0, %1, %2, %3;" : "=l"(d) : "l"(a), "l"(b), "l"(c)); return d;
}

// h1 = tanh(r*w1+b1); z2 = h1@W2+b2; h2 = tanh(z2); phi = h2.w3
// h1' = (1-h1^2)w1 ; h1'' = -2 h1 h1' w1
// h2' = (1-h2^2)z2' ; h2'' = (1-h2^2)z2'' - 2 h2 h2' z2'
template <bool DERIV>
__device__ __forceinline__ void mlp_pair(
    float r,
    const float* __restrict__ sW2, const float* __restrict__ sw1,
    const float* __restrict__ sb1, const float* __restrict__ sb2,
    const float* __restrict__ sw3, float* __restrict__ myh1,
    float& phi, float& dphi, float& d2phi)
{
    #pragma unroll 8
    for (int k = 0; k < HH; k++)
        myh1[k * 256] = tanhf(fmaf(r, sw1[k], sb1[k]));

    phi = 0.f; dphi = 0.f; d2phi = 0.f;

    for (int c = 0; c < HH; c += 16) {
        u64 z2[8], zp[8], zpp[8];
        #pragma unroll
        for (int p = 0; p < 8; p++) {
            z2[p]  = pack2f(sb2[c + 2 * p], sb2[c + 2 * p + 1]);
            zp[p]  = 0ull;
            zpp[p] = 0ull;
        }
        #pragma unroll 4
        for (int k = 0; k < HH; k++) {
            float h  = myh1[k * 256];
            u64 hh   = pack2(h);
            u64 hpx  = 0ull, hppx = 0ull;
            if (DERIV) {
                float w1k = sw1[k];
                float s   = fmaf(-h, h, 1.f);
                float hp  = s * w1k;
                float hpp = -2.f * h * hp * w1k;
                hpx  = pack2(hp);
                hppx = pack2(hpp);
            }
            const ulonglong2* wr = (const ulonglong2*)(sW2 + k * HH + c);
            #pragma unroll
            for (int q = 0; q < 4; q++) {
                ulonglong2 w = wr[q];
                z2[2 * q]     = fma2(w.x, hh, z2[2 * q]);
                z2[2 * q + 1] = fma2(w.y, hh, z2[2 * q + 1]);
                if (DERIV) {
                    zp[2 * q]      = fma2(w.x, hpx,  zp[2 * q]);
                    zp[2 * q + 1]  = fma2(w.y, hpx,  zp[2 * q + 1]);
                    zpp[2 * q]     = fma2(w.x, hppx, zpp[2 * q]);
                    zpp[2 * q + 1] = fma2(w.y, hppx, zpp[2 * q + 1]);
                }
            }
        }
        #pragma unroll
        for (int p = 0; p < 8; p++) {
            float a0, a1, p0 = 0.f, p1 = 0.f, q0 = 0.f, q1 = 0.f;
            unpack2(z2[p], a0, a1);
            if (DERIV) { unpack2(zp[p], p0, p1); unpack2(zpp[p], q0, q1); }
            float w30 = sw3[c + 2 * p], w31 = sw3[c + 2 * p + 1];

            float h2 = tanhf(a0);
            phi = fmaf(w30, h2, phi);
            if (DERIV) {
                float e   = fmaf(-h2, h2, 1.f);
                float hp2 = e * p0;
                float hq2 = fmaf(e, q0, -2.f * h2 * hp2 * p0);
                dphi  = fmaf(w30, hp2, dphi);
                d2phi = fmaf(w30, hq2, d2phi);
            }
            h2 = tanhf(a1);
            phi = fmaf(w31, h2, phi);
            if (DERIV) {
                float e   = fmaf(-h2, h2, 1.f);
                float hp2 = e * p1;
                float hq2 = fmaf(e, q1, -2.f * h2 * hp2 * p1);
                dphi  = fmaf(w31, hp2, dphi);
                d2phi = fmaf(w31, hq2, d2phi);
            }
        }
    }
}

__global__ void zero_gvec()
{
    int idx = blockIdx.x * 256 + threadIdx.x;
    if (idx < MM * LL * NN * 2) g_vec[idx] = 0.0;
}

__global__ void __launch_bounds__(256)
phi_loss_main(const float* __restrict__ data,
              const float* __restrict__ w1, const float* __restrict__ b1,
              const float* __restrict__ W2, const float* __restrict__ b2,
              const float* __restrict__ w3, const float* __restrict__ b3p)
{
    extern __shared__ float sh[];
    float* sW2 = sh;                 // HH*HH
    float* sw1 = sW2 + HH * HH;
    float* sb1 = sw1 + HH;
    float* sb2 = sb1 + HH;
    float* sw3 = sb2 + HH;
    float* h1s = sw3 + HH;           // HH * 256, layout [k][tid]
    __shared__ float2 red[256];

    int tid = threadIdx.x;
    for (int idx = tid; idx < HH * HH; idx += 256) sW2[idx] = W2[idx];
    if (tid < HH) { sw1[tid] = w1[tid]; sb1[tid] = b1[tid]; sb2[tid] = b2[tid]; sw3[tid] = w3[tid]; }
    __syncthreads();

    int sl = blockIdx.y;             // 0..11
    int m  = sl / LL;
    int l  = sl % LL;
    bool deriv   = (l < LL - 1);
    bool needphi = (l == 0 || l == LL - 1);

    // triangular pair decode: p -> (i < j)
    int p = blockIdx.x * 256 + tid;
    long long q = (long long)(NPAIR - 1 - p);
    int k = (int)((sqrt((double)(8.0 * (double)q + 1.0)) - 1.0) * 0.5);
    while ((long long)(k + 1) * (k + 2) / 2 <= q) k++;
    while ((long long)k * (k + 1) / 2 > q) k--;
    int i = (NN - 2) - k;
    int o = (int)(q - (long long)k * (k + 1) / 2);
    int j = (NN - 1) - o;

    const float* snap = data + ((size_t)(m * LL + l)) * NN * 2;
    float xi0 = snap[i * 2 + 0];
    float xi1 = snap[i * 2 + 1];
    float xj0 = snap[j * 2 + 0];
    float xj1 = snap[j * 2 + 1];
    float b3  = b3p[0];

    float dx = xi0 - xj0, dy = xi1 - xj1;
    float ssq = dx * dx + dy * dy;
    float r = (ssq > 0.f) ? sqrtf(ssq) : 0.f;

    float phi, dphi, d2phi;
    float* myh1 = h1s + tid;
    if (deriv) mlp_pair<true >(r, sW2, sw1, sb1, sb2, sw3, myh1, phi, dphi, d2phi);
    else       mlp_pair<false>(r, sW2, sw1, sb1, sb2, sw3, myh1, phi, dphi, d2phi);

    float lap2 = 0.f, phi2 = 0.f;
    if (needphi) phi2 = 2.f * (phi + b3);
    if (deriv) {
        lap2 = 2.f * d2phi;
        float inv = 1.f / fmaxf(r, 1e-10f);
        float cx = dphi * inv * dx;
        float cy = dphi * inv * dy;
        double* gv = g_vec + ((size_t)(m * LL + l) * NN) * 2;
        atomicAdd(&gv[i * 2 + 0],  (double)cx);
        atomicAdd(&gv[i * 2 + 1],  (double)cy);
        atomicAdd(&gv[j * 2 + 0], -(double)cx);
        atomicAdd(&gv[j * 2 + 1], -(double)cy);
    }

    red[tid] = make_float2(lap2, phi2);
    __syncthreads();
    for (int s = 128; s > 0; s >>= 1) {
        if (tid < s) {
            float2 a = red[tid], c = red[tid + s];
            red[tid] = make_float2(a.x + c.x, a.y + c.y);
        }
        __syncthreads();
    }
    if (tid == 0) {
        g_lap[sl * PBLK + blockIdx.x] = (double)red[0].x;
        g_phi[sl * PBLK + blockIdx.x] = (double)red[0].y;
    }
}

__global__ void __launch_bounds__(256)
phi_loss_finalize(const float* __restrict__ data, const float* __restrict__ t,
                  float* __restrict__ out)
{
    __shared__ double red[256];
    int tid = threadIdx.x;
    double s = 0.0;
    const double invN  = 1.0 / (double)NN;
    const double invN2 = invN * invN;

    // scalar block partials: laplacian (l<5) and phi at l=0/5
    for (int idx = tid; idx < 12 * PBLK; idx += 256) {
        int sl = idx / PBLK;
        int l  = sl % LL;
        if (l < LL - 1) {
            double dt = (double)(t[l + 1] - t[l]);
            s += SIG2 * dt * g_lap[idx] * invN2;
        }
        if (l == 0)      s += 2.0 * g_phi[idx] * invN2;
        if (l == LL - 1) s -= 2.0 * g_phi[idx] * invN2;
    }

    // dissipation: drift^2 over m, l<5, i
    for (int idx = tid; idx < MM * (LL - 1) * NN; idx += 256) {
        int i  = idx % NN;
        int ml = idx / NN;
        int l  = ml % (LL - 1);
        int m  = ml / (LL - 1);
        const float* snap = data + ((size_t)(m * LL + l)) * NN * 2;
        const double* gv = g_vec + ((size_t)(m * LL + l) * NN + i) * 2;
        double dt = (double)(t[l + 1] - t[l]);
        double drx = -(double)VK * (double)snap[i * 2 + 0] - gv[0] * invN;
        double dry = -(double)VK * (double)snap[i * 2 + 1] - gv[1] * invN;
        s += dt * (drx * drx + dry * dry) * invN;
    }

    // energy V terms at l=0 (+2) and l=5 (-2)
    for (int idx = tid; idx < MM * 2 * NN; idx += 256) {
        int i  = idx % NN;
        int le = (idx / NN) % 2;          // 0 -> l=0, 1 -> l=5
        int m  = idx / (2 * NN);
        int l  = le ? (LL - 1) : 0;
        double sign = le ? -2.0 : 2.0;
        const float* snap = data + ((size_t)(m * LL + l)) * NN * 2;
        double x = snap[i * 2 + 0], y = snap[i * 2 + 1];
        s += sign * 0.5 * (double)VK * (x * x + y * y) * invN;
    }

    red[tid] = s;
    __syncthreads();
    for (int k = 128; k > 0; k >>= 1) {
        if (tid < k) red[tid] += red[tid + k];
        __syncthreads();
    }
    if (tid == 0) {
        double S = red[0];
        // constant diffusion term: SIG2*VK*d*dt summed over m,l (telescopes in t)
        S += (double)MM * SIG2 * (double)VK * DDIM * (double)(t[LL - 1] - t[0]);
        double res = S / (double)(MM * (LL - 1));
        out[0] = (float)(res * res);
    }
}

extern "C" void kernel_launch(void* const* d_in, const int* in_sizes, int n_in,
                              void* d_out, int out_size)
{
    const float* data = (const float*)d_in[0];
    const float* t    = (const float*)d_in[1];
    const float* w1   = (const float*)d_in[2];
    const float* b1   = (const float*)d_in[3];
    const float* W2   = (const float*)d_in[4];
    const float* b2   = (const float*)d_in[5];
    const float* w3   = (const float*)d_in[6];
    const float* b3   = (const float*)d_in[7];

    size_t smem = (size_t)(HH * HH + 4 * HH + HH * 256) * sizeof(float);  // 82944 B
    cudaFuncSetAttribute(phi_loss_main, cudaFuncAttributeMaxDynamicSharedMemorySize, (int)smem);

    zero_gvec<<<(MM * LL * NN * 2 + 255) / 256, 256>>>();
    dim3 grid(PBLK, 12);
    phi_loss_main<<<grid, 256, smem>>>(data, w1, b1, W2, b2, w3, b3);
    phi_loss_finalize<<<1, 256>>>(data, t, (float*)d_out);
}

// round 3
// speedup vs baseline: 1.9593x; 1.0847x over previous
#include <cuda_runtime.h>

#define MM 2
#define LL 6
#define NN 512
#define HH 64
#define VK 1.0f
#define SIG2 0.01
#define DDIM 2.0
#define NPAIR 130816          // 512*511/2 = 511*256
#define PBLK 511              // pair-blocks per snapshot

typedef unsigned long long u64;

// per-block scalar partials (deterministic reduction in finalize)
__device__ double g_lap[12 * PBLK];
__device__ double g_phi[12 * PBLK];
// gradient accumulator, double atomics (order-independent to ~1e-16)
__device__ double g_vec[MM * LL * NN * 2];

__device__ __forceinline__ float tanh_fast(float x) {
    float y; asm("tanh.approx.f32 %0, %1;" : "=f"(y) : "f"(x)); return y;
}
__device__ __forceinline__ u64 pack2(float x) {
    u64 r; asm("mov.b64 %0, {%1,%1};" : "=l"(r) : "f"(x)); return r;
}
__device__ __forceinline__ u64 pack2f(float lo, float hi) {
    u64 r; asm("mov.b64 %0, {%1,%2};" : "=l"(r) : "f"(lo), "f"(hi)); return r;
}
__device__ __forceinline__ void unpack2(u64 v, float& lo, float& hi) {
    asm("mov.b64 {%0,%1}, %2;" : "=f"(lo), "=f"(hi) : "l"(v));
}
__device__ __forceinline__ u64 fma2(u64 a, u64 b, u64 c) {
    u64 d; asm("fma.rn.f32x2 %0, %1, %2, %3;" : "=l"(d) : "l"(a), "l"(b), "l"(c)); return d;
}

// h1 = tanh(r*w1+b1); z2 = h1@W2+b2; h2 = tanh(z2); phi = h2.w3
// h1' = (1-h1^2)w1 ; h1'' = -2 h1 h1' w1
// h2' = (1-h2^2)z2' ; h2'' = (1-h2^2)z2'' - 2 h2 h2' z2'
template <bool DERIV>
__device__ __forceinline__ void mlp_pair(
    float r,
    const float* __restrict__ sW2, const float* __restrict__ sw1,
    const float* __restrict__ sb1, const float* __restrict__ sb2,
    const float* __restrict__ sw3, float* __restrict__ myh1,
    float& phi, float& dphi, float& d2phi)
{
    #pragma unroll 16
    for (int k = 0; k < HH; k++)
        myh1[k * 256] = tanh_fast(fmaf(r, sw1[k], sb1[k]));

    phi = 0.f; dphi = 0.f; d2phi = 0.f;

    for (int c = 0; c < HH; c += 16) {
        u64 z2[8], zp[8], zpp[8];
        #pragma unroll
        for (int p = 0; p < 8; p++) {
            z2[p]  = pack2f(sb2[c + 2 * p], sb2[c + 2 * p + 1]);
            zp[p]  = 0ull;
            zpp[p] = 0ull;
        }
        #pragma unroll 4
        for (int k = 0; k < HH; k++) {
            float h  = myh1[k * 256];
            u64 hh   = pack2(h);
            u64 hpx  = 0ull, hppx = 0ull;
            if (DERIV) {
                float w1k = sw1[k];
                float s   = fmaf(-h, h, 1.f);
                float hp  = s * w1k;
                float hpp = -2.f * h * hp * w1k;
                hpx  = pack2(hp);
                hppx = pack2(hpp);
            }
            const ulonglong2* wr = (const ulonglong2*)(sW2 + k * HH + c);
            #pragma unroll
            for (int q = 0; q < 4; q++) {
                ulonglong2 w = wr[q];
                z2[2 * q]     = fma2(w.x, hh, z2[2 * q]);
                z2[2 * q + 1] = fma2(w.y, hh, z2[2 * q + 1]);
                if (DERIV) {
                    zp[2 * q]      = fma2(w.x, hpx,  zp[2 * q]);
                    zp[2 * q + 1]  = fma2(w.y, hpx,  zp[2 * q + 1]);
                    zpp[2 * q]     = fma2(w.x, hppx, zpp[2 * q]);
                    zpp[2 * q + 1] = fma2(w.y, hppx, zpp[2 * q + 1]);
                }
            }
        }
        #pragma unroll
        for (int p = 0; p < 8; p++) {
            float a0, a1, p0 = 0.f, p1 = 0.f, q0 = 0.f, q1 = 0.f;
            unpack2(z2[p], a0, a1);
            if (DERIV) { unpack2(zp[p], p0, p1); unpack2(zpp[p], q0, q1); }
            float w30 = sw3[c + 2 * p], w31 = sw3[c + 2 * p + 1];

            float h2 = tanh_fast(a0);
            phi = fmaf(w30, h2, phi);
            if (DERIV) {
                float e   = fmaf(-h2, h2, 1.f);
                float hp2 = e * p0;
                float hq2 = fmaf(e, q0, -2.f * h2 * hp2 * p0);
                dphi  = fmaf(w30, hp2, dphi);
                d2phi = fmaf(w30, hq2, d2phi);
            }
            h2 = tanh_fast(a1);
            phi = fmaf(w31, h2, phi);
            if (DERIV) {
                float e   = fmaf(-h2, h2, 1.f);
                float hp2 = e * p1;
                float hq2 = fmaf(e, q1, -2.f * h2 * hp2 * p1);
                dphi  = fmaf(w31, hp2, dphi);
                d2phi = fmaf(w31, hq2, d2phi);
            }
        }
    }
}

__global__ void zero_gvec()
{
    int idx = blockIdx.x * 256 + threadIdx.x;
    if (idx < MM * LL * NN * 2) g_vec[idx] = 0.0;
}

__global__ void __launch_bounds__(256)
phi_loss_main(const float* __restrict__ data,
              const float* __restrict__ w1, const float* __restrict__ b1,
              const float* __restrict__ W2, const float* __restrict__ b2,
              const float* __restrict__ w3, const float* __restrict__ b3p)
{
    extern __shared__ float sh[];
    float* sW2 = sh;                 // HH*HH
    float* sw1 = sW2 + HH * HH;
    float* sb1 = sw1 + HH;
    float* sb2 = sb1 + HH;
    float* sw3 = sb2 + HH;
    float* h1s = sw3 + HH;           // HH * 256, layout [k][tid]
    __shared__ float2 red[256];

    int tid = threadIdx.x;
    for (int idx = tid; idx < HH * HH; idx += 256) sW2[idx] = W2[idx];
    if (tid < HH) { sw1[tid] = w1[tid]; sb1[tid] = b1[tid]; sb2[tid] = b2[tid]; sw3[tid] = w3[tid]; }
    __syncthreads();

    int sl = blockIdx.y;             // 0..11
    int m  = sl / LL;
    int l  = sl % LL;
    bool deriv   = (l < LL - 1);
    bool needphi = (l == 0 || l == LL - 1);

    // triangular pair decode: p -> (i < j)
    int p = blockIdx.x * 256 + tid;
    long long q = (long long)(NPAIR - 1 - p);
    int k = (int)((sqrt((double)(8.0 * (double)q + 1.0)) - 1.0) * 0.5);
    while ((long long)(k + 1) * (k + 2) / 2 <= q) k++;
    while ((long long)k * (k + 1) / 2 > q) k--;
    int i = (NN - 2) - k;
    int o = (int)(q - (long long)k * (k + 1) / 2);
    int j = (NN - 1) - o;

    const float* snap = data + ((size_t)(m * LL + l)) * NN * 2;
    float xi0 = snap[i * 2 + 0];
    float xi1 = snap[i * 2 + 1];
    float xj0 = snap[j * 2 + 0];
    float xj1 = snap[j * 2 + 1];
    float b3  = b3p[0];

    float dx = xi0 - xj0, dy = xi1 - xj1;
    float ssq = dx * dx + dy * dy;
    float r = (ssq > 0.f) ? sqrtf(ssq) : 0.f;

    float phi, dphi, d2phi;
    float* myh1 = h1s + tid;
    if (deriv) mlp_pair<true >(r, sW2, sw1, sb1, sb2, sw3, myh1, phi, dphi, d2phi);
    else       mlp_pair<false>(r, sW2, sw1, sb1, sb2, sw3, myh1, phi, dphi, d2phi);

    float lap2 = 0.f, phi2 = 0.f;
    if (needphi) phi2 = 2.f * (phi + b3);
    if (deriv) {
        lap2 = 2.f * d2phi;
        float inv = 1.f / fmaxf(r, 1e-10f);
        float cx = dphi * inv * dx;
        float cy = dphi * inv * dy;
        double* gv = g_vec + ((size_t)(m * LL + l) * NN) * 2;
        atomicAdd(&gv[i * 2 + 0],  (double)cx);
        atomicAdd(&gv[i * 2 + 1],  (double)cy);
        atomicAdd(&gv[j * 2 + 0], -(double)cx);
        atomicAdd(&gv[j * 2 + 1], -(double)cy);
    }

    red[tid] = make_float2(lap2, phi2);
    __syncthreads();
    for (int s = 128; s > 0; s >>= 1) {
        if (tid < s) {
            float2 a = red[tid], c = red[tid + s];
            red[tid] = make_float2(a.x + c.x, a.y + c.y);
        }
        __syncthreads();
    }
    if (tid == 0) {
        g_lap[sl * PBLK + blockIdx.x] = (double)red[0].x;
        g_phi[sl * PBLK + blockIdx.x] = (double)red[0].y;
    }
}

__global__ void __launch_bounds__(256)
phi_loss_finalize(const float* __restrict__ data, const float* __restrict__ t,
                  float* __restrict__ out)
{
    __shared__ double red[256];
    int tid = threadIdx.x;
    double s = 0.0;
    const double invN  = 1.0 / (double)NN;
    const double invN2 = invN * invN;

    // scalar block partials: laplacian (l<5) and phi at l=0/5
    for (int idx = tid; idx < 12 * PBLK; idx += 256) {
        int sl = idx / PBLK;
        int l  = sl % LL;
        if (l < LL - 1) {
            double dt = (double)(t[l + 1] - t[l]);
            s += SIG2 * dt * g_lap[idx] * invN2;
        }
        if (l == 0)      s += 2.0 * g_phi[idx] * invN2;
        if (l == LL - 1) s -= 2.0 * g_phi[idx] * invN2;
    }

    // dissipation: drift^2 over m, l<5, i
    for (int idx = tid; idx < MM * (LL - 1) * NN; idx += 256) {
        int i  = idx % NN;
        int ml = idx / NN;
        int l  = ml % (LL - 1);
        int m  = ml / (LL - 1);
        const float* snap = data + ((size_t)(m * LL + l)) * NN * 2;
        const double* gv = g_vec + ((size_t)(m * LL + l) * NN + i) * 2;
        double dt = (double)(t[l + 1] - t[l]);
        double drx = -(double)VK * (double)snap[i * 2 + 0] - gv[0] * invN;
        double dry = -(double)VK * (double)snap[i * 2 + 1] - gv[1] * invN;
        s += dt * (drx * drx + dry * dry) * invN;
    }

    // energy V terms at l=0 (+2) and l=5 (-2)
    for (int idx = tid; idx < MM * 2 * NN; idx += 256) {
        int i  = idx % NN;
        int le = (idx / NN) % 2;          // 0 -> l=0, 1 -> l=5
        int m  = idx / (2 * NN);
        int l  = le ? (LL - 1) : 0;
        double sign = le ? -2.0 : 2.0;
        const float* snap = data + ((size_t)(m * LL + l)) * NN * 2;
        double x = snap[i * 2 + 0], y = snap[i * 2 + 1];
        s += sign * 0.5 * (double)VK * (x * x + y * y) * invN;
    }

    red[tid] = s;
    __syncthreads();
    for (int k = 128; k > 0; k >>= 1) {
        if (tid < k) red[tid] += red[tid + k];
        __syncthreads();
    }
    if (tid == 0) {
        double S = red[0];
        // constant diffusion term: SIG2*VK*d*dt summed over m,l (telescopes in t)
        S += (double)MM * SIG2 * (double)VK * DDIM * (double)(t[LL - 1] - t[0]);
        double res = S / (double)(MM * (LL - 1));
        out[0] = (float)(res * res);
    }
}

extern "C" void kernel_launch(void* const* d_in, const int* in_sizes, int n_in,
                              void* d_out, int out_size)
{
    const float* data = (const float*)d_in[0];
    const float* t    = (const float*)d_in[1];
    const float* w1   = (const float*)d_in[2];
    const float* b1   = (const float*)d_in[3];
    const float* W2   = (const float*)d_in[4];
    const float* b2   = (const float*)d_in[5];
    const float* w3   = (const float*)d_in[6];
    const float* b3   = (const float*)d_in[7];

    size_t smem = (size_t)(HH * HH + 4 * HH + HH * 256) * sizeof(float);  // 82944 B
    cudaFuncSetAttribute(phi_loss_main, cudaFuncAttributeMaxDynamicSharedMemorySize, (int)smem);

    zero_gvec<<<(MM * LL * NN * 2 + 255) / 256, 256>>>();
    dim3 grid(PBLK, 12);
    phi_loss_main<<<grid, 256, smem>>>(data, w1, b1, W2, b2, w3, b3);
    phi_loss_finalize<<<1, 256>>>(data, t, (float*)d_out);
}

// round 5
// speedup vs baseline: 19.4874x; 9.9460x over previous
#include <cuda_runtime.h>
#include <cstdint>

#define MM 2
#define LL 6
#define NN 512
#define HH 64
#define VK 1.0f
#define SIG2 0.01
#define DDIM 2.0
#define NT 65536
#define RMAX 16.0f

typedef unsigned long long u64;

// per-(m,l,i) block partial; fixed-order reduction -> deterministic
__device__ double g_parts[MM * LL * NN];
// lookup table: (phi+b3, dphi, d2phi, 0) on r = idx * RMAX/NT
__device__ float4 g_tab[NT];

__device__ __forceinline__ u64 pack2(float x) {
    u64 r; asm("mov.b64 %0, {%1,%1};" : "=l"(r) : "f"(x)); return r;
}
__device__ __forceinline__ u64 pack2f(float lo, float hi) {
    u64 r; asm("mov.b64 %0, {%1,%2};" : "=l"(r) : "f"(lo), "f"(hi)); return r;
}
__device__ __forceinline__ void unpack2(u64 v, float& lo, float& hi) {
    asm("mov.b64 {%0,%1}, %2;" : "=f"(lo), "=f"(hi) : "l"(v));
}
__device__ __forceinline__ u64 fma2(u64 a, u64 b, u64 c) {
    u64 d; asm("fma.rn.f32x2 %0, %1, %2, %3;" : "=l"(d) : "l"(a), "l"(b), "l"(c)); return d;
}

// exact-fp32 MLP + first/second derivative at scalar r (same math as validated R1-R3)
__device__ __forceinline__ void mlp_eval(
    float r,
    const float* __restrict__ sW2, const float* __restrict__ sw1,
    const float* __restrict__ sb1, const float* __restrict__ sb2,
    const float* __restrict__ sw3, float* __restrict__ myh1,
    float& phi, float& dphi, float& d2phi)
{
    #pragma unroll 8
    for (int k = 0; k < HH; k++)
        myh1[k * 256] = tanhf(fmaf(r, sw1[k], sb1[k]));

    phi = 0.f; dphi = 0.f; d2phi = 0.f;

    for (int c = 0; c < HH; c += 16) {
        u64 z2[8], zp[8], zpp[8];
        #pragma unroll
        for (int p = 0; p < 8; p++) {
            z2[p]  = pack2f(sb2[c + 2 * p], sb2[c + 2 * p + 1]);
            zp[p]  = 0ull;
            zpp[p] = 0ull;
        }
        #pragma unroll 4
        for (int k = 0; k < HH; k++) {
            float h  = myh1[k * 256];
            u64 hh   = pack2(h);
            float w1k = sw1[k];
            float s   = fmaf(-h, h, 1.f);
            float hp  = s * w1k;
            float hpp = -2.f * h * hp * w1k;
            u64 hpx  = pack2(hp);
            u64 hppx = pack2(hpp);
            const ulonglong2* wr = (const ulonglong2*)(sW2 + k * HH + c);
            #pragma unroll
            for (int q = 0; q < 4; q++) {
                ulonglong2 w = wr[q];
                z2[2 * q]      = fma2(w.x, hh,   z2[2 * q]);
                z2[2 * q + 1]  = fma2(w.y, hh,   z2[2 * q + 1]);
                zp[2 * q]      = fma2(w.x, hpx,  zp[2 * q]);
                zp[2 * q + 1]  = fma2(w.y, hpx,  zp[2 * q + 1]);
                zpp[2 * q]     = fma2(w.x, hppx, zpp[2 * q]);
                zpp[2 * q + 1] = fma2(w.y, hppx, zpp[2 * q + 1]);
            }
        }
        #pragma unroll
        for (int p = 0; p < 8; p++) {
            float a0, a1, p0, p1, q0, q1;
            unpack2(z2[p], a0, a1);
            unpack2(zp[p], p0, p1);
            unpack2(zpp[p], q0, q1);
            float w30 = sw3[c + 2 * p], w31 = sw3[c + 2 * p + 1];

            float h2 = tanhf(a0);
            phi = fmaf(w30, h2, phi);
            float e   = fmaf(-h2, h2, 1.f);
            float hp2 = e * p0;
            float hq2 = fmaf(e, q0, -2.f * h2 * hp2 * p0);
            dphi  = fmaf(w30, hp2, dphi);
            d2phi = fmaf(w30, hq2, d2phi);

            h2 = tanhf(a1);
            phi = fmaf(w31, h2, phi);
            e   = fmaf(-h2, h2, 1.f);
            hp2 = e * p1;
            hq2 = fmaf(e, q1, -2.f * h2 * hp2 * p1);
            dphi  = fmaf(w31, hp2, dphi);
            d2phi = fmaf(w31, hq2, d2phi);
        }
    }
}

__global__ void __launch_bounds__(256)
build_table(const float* __restrict__ w1, const float* __restrict__ b1,
            const float* __restrict__ W2, const float* __restrict__ b2,
            const float* __restrict__ w3, const float* __restrict__ b3p)
{
    extern __shared__ float sh[];
    float* sW2 = sh;                 // HH*HH
    float* sw1 = sW2 + HH * HH;
    float* sb1 = sw1 + HH;
    float* sb2 = sb1 + HH;
    float* sw3 = sb2 + HH;
    float* h1s = sw3 + HH;           // HH * 256

    int tid = threadIdx.x;
    for (int idx = tid; idx < HH * HH; idx += 256) sW2[idx] = W2[idx];
    if (tid < HH) { sw1[tid] = w1[tid]; sb1[tid] = b1[tid]; sb2[tid] = b2[tid]; sw3[tid] = w3[tid]; }
    __syncthreads();

    int idx = blockIdx.x * 256 + tid;
    float r = (float)idx * (RMAX / (float)NT);
    float phi, dphi, d2phi;
    mlp_eval(r, sW2, sw1, sb1, sb2, sw3, h1s + tid, phi, dphi, d2phi);
    g_tab[idx] = make_float4(phi + b3p[0], dphi, d2phi, 0.f);
}

__global__ void __launch_bounds__(256)
pair_pass(const float* __restrict__ data, const float* __restrict__ t)
{
    __shared__ float2 sx[NN];
    __shared__ float4 red[256];

    int tid = threadIdx.x;
    int b = blockIdx.x;
    int i = b % NN;
    int l = (b / NN) % LL;
    int m = b / (NN * LL);
    bool deriv   = (l < LL - 1);
    bool needphi = (l == 0 || l == LL - 1);

    const float2* snap = (const float2*)(data + ((size_t)(m * LL + l)) * NN * 2);
    sx[tid]       = snap[tid];
    sx[tid + 256] = snap[tid + 256];
    __syncthreads();

    float2 xi = sx[i];
    float gx = 0.f, gy = 0.f, lap = 0.f, phis = 0.f;
    const float scale = (float)NT / RMAX;

    #pragma unroll
    for (int jj = 0; jj < 2; jj++) {
        int j = tid + jj * 256;
        float2 xj = sx[j];
        float dx = xi.x - xj.x, dy = xi.y - xj.y;
        float ssq = dx * dx + dy * dy;
        if (j != i) {
            float r = sqrtf(ssq);
            float u = r * scale;
            int i0 = (int)u;
            i0 = (i0 > NT - 2) ? (NT - 2) : i0;
            float f = u - (float)i0;
            float4 t0 = __ldg(&g_tab[i0]);
            float4 t1 = __ldg(&g_tab[i0 + 1]);
            float phi  = fmaf(f, t1.x - t0.x, t0.x);
            float dphi = fmaf(f, t1.y - t0.y, t0.y);
            float d2   = fmaf(f, t1.z - t0.z, t0.z);
            phis += phi;
            lap  += d2;
            float inv = 1.f / fmaxf(r, 1e-10f);
            gx = fmaf(dphi * inv, dx, gx);
            gy = fmaf(dphi * inv, dy, gy);
        }
    }

    red[tid] = make_float4(gx, gy, lap, phis);
    __syncthreads();
    for (int s = 128; s > 0; s >>= 1) {
        if (tid < s) {
            float4 a = red[tid], c = red[tid + s];
            red[tid] = make_float4(a.x + c.x, a.y + c.y, a.z + c.z, a.w + c.w);
        }
        __syncthreads();
    }

    if (tid == 0) {
        float4 tot = red[0];
        double contrib = 0.0;
        if (deriv) {
            float dtl = t[l + 1] - t[l];
            float dgx = fmaf(-VK, xi.x, -tot.x / NN);   // drift_x
            float dgy = fmaf(-VK, xi.y, -tot.y / NN);   // drift_y
            contrib += (double)dtl * ((double)dgx * dgx + (double)dgy * dgy) / NN;   // diss
            contrib += SIG2 * (double)dtl * ((double)tot.z / NN) / NN;               // diff (lap)
        }
        if (needphi) {
            double sign = (l == 0) ? 2.0 : -2.0;        // -2*(E_last - E_first)
            contrib += sign * ((double)tot.w / ((double)NN * NN)
                             + 0.5 * (double)VK * ((double)xi.x * xi.x + (double)xi.y * xi.y) / NN);
        }
        g_parts[b] = contrib;
    }
}

__global__ void __launch_bounds__(256)
phi_loss_finalize(const float* __restrict__ t, float* __restrict__ out)
{
    __shared__ double red[256];
    int tid = threadIdx.x;
    double s = 0.0;
    for (int idx = tid; idx < MM * LL * NN; idx += 256) s += g_parts[idx];
    red[tid] = s;
    __syncthreads();
    for (int k = 128; k > 0; k >>= 1) {
        if (tid < k) red[tid] += red[tid + k];
        __syncthreads();
    }
    if (tid == 0) {
        double S = red[0];
        // constant diffusion term: SIG2*VK*d*dt summed over m,l (telescopes in t)
        S += (double)MM * SIG2 * (double)VK * DDIM * (double)(t[LL - 1] - t[0]);
        double res = S / (double)(MM * (LL - 1));
        out[0] = (float)(res * res);
    }
}

extern "C" void kernel_launch(void* const* d_in, const int* in_sizes, int n_in,
                              void* d_out, int out_size)
{
    const float* data = (const float*)d_in[0];
    const float* t    = (const float*)d_in[1];
    const float* w1   = (const float*)d_in[2];
    const float* b1   = (const float*)d_in[3];
    const float* W2   = (const float*)d_in[4];
    const float* b2   = (const float*)d_in[5];
    const float* w3   = (const float*)d_in[6];
    const float* b3   = (const float*)d_in[7];

    size_t smem = (size_t)(HH * HH + 4 * HH + HH * 256) * sizeof(float);  // 82944 B
    cudaFuncSetAttribute(build_table, cudaFuncAttributeMaxDynamicSharedMemorySize, (int)smem);

    build_table<<<NT / 256, 256, smem>>>(w1, b1, W2, b2, w3, b3);
    pair_pass<<<MM * LL * NN, 256>>>(data, t);
    phi_loss_finalize<<<1, 256>>>(t, (float*)d_out);
}

// round 7
// speedup vs baseline: 33.5652x; 1.7224x over previous
#include <cuda_runtime.h>
#include <cstdint>

#define MM 2
#define LL 6
#define NN 512
#define HH 64
#define VK 1.0f
#define SIG2 0.01
#define DDIM 2.0
#define NT 8192
#define RMAX 16.0f
#define NBLK (MM * LL * NN)       // 6144 pair blocks

typedef unsigned long long u64;

__device__ float4 g_tab[NT];      // (phi+b3, dphi, d2phi, 0) at r = idx*RMAX/NT
__device__ double g_slots[64];
__device__ unsigned g_cnt;

__device__ __forceinline__ float tanh_fast(float x) {
    float y; asm("tanh.approx.f32 %0, %1;" : "=f"(y) : "f"(x)); return y;
}
__device__ __forceinline__ u64 pack2(float x) {
    u64 r; asm("mov.b64 %0, {%1,%1};" : "=l"(r) : "f"(x)); return r;
}
__device__ __forceinline__ u64 pack2f(float lo, float hi) {
    u64 r; asm("mov.b64 %0, {%1,%2};" : "=l"(r) : "f"(lo), "f"(hi)); return r;
}
__device__ __forceinline__ void unpack2(u64 v, float& lo, float& hi) {
    asm("mov.b64 {%0,%1}, %2;" : "=f"(lo), "=f"(hi) : "l"(v));
}
__device__ __forceinline__ u64 fma2(u64 a, u64 b, u64 c) {
    u64 d; asm("fma.rn.f32x2 %0, %1, %2, %3;" : "=l"(d) : "l"(a), "l"(b), "l"(c)); return d;
}

// ---------------- builder: 2 lanes per r (each does 32 of 64 channels) ----------------
__global__ void __launch_bounds__(128)
build_table(const float* __restrict__ w1, const float* __restrict__ b1,
            const float* __restrict__ W2, const float* __restrict__ b2,
            const float* __restrict__ w3, const float* __restrict__ b3p)
{
    __shared__ float sW2[HH * HH];
    __shared__ float sw1[HH], sb1[HH], sb2[HH], sw3[HH];
    __shared__ float h1s[HH * 64];      // [k][pair], 64 pairs per block

    int tid = threadIdx.x;
    #pragma unroll
    for (int s = 0; s < HH * HH; s += 128) sW2[s + tid] = W2[s + tid];
    if (tid < HH) { sw1[tid] = w1[tid]; sb1[tid] = b1[tid]; sb2[tid] = b2[tid]; sw3[tid] = w3[tid]; }

    // reset accumulation state for this launch (pair_pass runs after this kernel)
    if (blockIdx.x == 0) {
        if (tid < 64) g_slots[tid] = 0.0;
        if (tid == 64) g_cnt = 0u;
    }
    __syncthreads();   // params visible to ALL warps before h1 computation (R6 bug fix)

    int gt   = blockIdx.x * 128 + tid;
    int ridx = gt >> 1;
    int half = gt & 1;
    int pair = tid >> 1;
    float r = (float)ridx * (RMAX / (float)NT);

    // layer 1 (split across the two lanes of the pair)
    int kbase = half * 32;
    #pragma unroll 8
    for (int k = kbase; k < kbase + 32; k++)
        h1s[k * 64 + pair] = tanh_fast(fmaf(r, sw1[k], sb1[k]));
    __syncthreads();

    float phi = 0.f, dphi = 0.f, d2phi = 0.f;

    #pragma unroll
    for (int cc = 0; cc < 2; cc++) {
        int c = half * 32 + cc * 16;
        u64 z2[8], zp[8], zpp[8];
        #pragma unroll
        for (int p = 0; p < 8; p++) {
            z2[p]  = pack2f(sb2[c + 2 * p], sb2[c + 2 * p + 1]);
            zp[p]  = 0ull;
            zpp[p] = 0ull;
        }
        #pragma unroll 4
        for (int k = 0; k < HH; k++) {
            float h   = h1s[k * 64 + pair];
            float w1k = sw1[k];
            float s   = fmaf(-h, h, 1.f);
            float hp  = s * w1k;
            float hpp = -2.f * h * hp * w1k;
            u64 hh   = pack2(h);
            u64 hpx  = pack2(hp);
            u64 hppx = pack2(hpp);
            const ulonglong2* wr = (const ulonglong2*)(sW2 + k * HH + c);
            #pragma unroll
            for (int q = 0; q < 4; q++) {
                ulonglong2 w = wr[q];
                z2[2 * q]      = fma2(w.x, hh,   z2[2 * q]);
                z2[2 * q + 1]  = fma2(w.y, hh,   z2[2 * q + 1]);
                zp[2 * q]      = fma2(w.x, hpx,  zp[2 * q]);
                zp[2 * q + 1]  = fma2(w.y, hpx,  zp[2 * q + 1]);
                zpp[2 * q]     = fma2(w.x, hppx, zpp[2 * q]);
                zpp[2 * q + 1] = fma2(w.y, hppx, zpp[2 * q + 1]);
            }
        }
        #pragma unroll
        for (int p = 0; p < 8; p++) {
            float a0, a1, p0, p1, q0, q1;
            unpack2(z2[p], a0, a1);
            unpack2(zp[p], p0, p1);
            unpack2(zpp[p], q0, q1);
            float w30 = sw3[c + 2 * p], w31 = sw3[c + 2 * p + 1];

            float h2 = tanh_fast(a0);
            phi = fmaf(w30, h2, phi);
            float e   = fmaf(-h2, h2, 1.f);
            float hp2 = e * p0;
            float hq2 = fmaf(e, q0, -2.f * h2 * hp2 * p0);
            dphi  = fmaf(w30, hp2, dphi);
            d2phi = fmaf(w30, hq2, d2phi);

            h2 = tanh_fast(a1);
            phi = fmaf(w31, h2, phi);
            e   = fmaf(-h2, h2, 1.f);
            hp2 = e * p1;
            hq2 = fmaf(e, q1, -2.f * h2 * hp2 * p1);
            dphi  = fmaf(w31, hp2, dphi);
            d2phi = fmaf(w31, hq2, d2phi);
        }
    }

    // combine the two half-lanes
    phi   += __shfl_xor_sync(0xffffffffu, phi,   1);
    dphi  += __shfl_xor_sync(0xffffffffu, dphi,  1);
    d2phi += __shfl_xor_sync(0xffffffffu, d2phi, 1);

    if (half == 0)
        g_tab[ridx] = make_float4(phi + b3p[0], dphi, d2phi, 0.f);
}

// ---------------- pair pass + in-kernel final reduction ----------------
__global__ void __launch_bounds__(256)
pair_pass(const float* __restrict__ data, const float* __restrict__ t,
          float* __restrict__ out)
{
    __shared__ float2 sx[NN];
    __shared__ float4 wred[8];
    __shared__ double sdbl[64];
    __shared__ unsigned is_last;

    int tid = threadIdx.x;
    int b = blockIdx.x;
    int i = b % NN;
    int l = (b / NN) % LL;
    int m = b / (NN * LL);
    bool deriv   = (l < LL - 1);
    bool needphi = (l == 0 || l == LL - 1);

    const float2* snap = (const float2*)(data + ((size_t)(m * LL + l)) * NN * 2);
    sx[tid]       = snap[tid];
    sx[tid + 256] = snap[tid + 256];
    __syncthreads();

    float2 xi = sx[i];
    float gx = 0.f, gy = 0.f, lap = 0.f, phis = 0.f;
    const float scale = (float)NT / RMAX;

    #pragma unroll
    for (int jj = 0; jj < 2; jj++) {
        int j = tid + jj * 256;
        float2 xj = sx[j];
        float dx = xi.x - xj.x, dy = xi.y - xj.y;
        float ssq = dx * dx + dy * dy;
        if (j != i) {
            float inv = rsqrtf(fmaxf(ssq, 1e-20f));
            float r = ssq * inv;
            float u = r * scale;
            int i0 = (int)u;
            i0 = (i0 > NT - 2) ? (NT - 2) : i0;
            float f = u - (float)i0;
            float4 t0 = __ldg(&g_tab[i0]);
            float4 t1 = __ldg(&g_tab[i0 + 1]);
            float phi  = fmaf(f, t1.x - t0.x, t0.x);
            float dphi = fmaf(f, t1.y - t0.y, t0.y);
            float d2   = fmaf(f, t1.z - t0.z, t0.z);
            phis += phi;
            lap  += d2;
            float c = dphi * inv;
            gx = fmaf(c, dx, gx);
            gy = fmaf(c, dy, gy);
        }
    }

    // warp shuffle reduction of (gx, gy, lap, phis)
    #pragma unroll
    for (int s = 16; s > 0; s >>= 1) {
        gx   += __shfl_xor_sync(0xffffffffu, gx,   s);
        gy   += __shfl_xor_sync(0xffffffffu, gy,   s);
        lap  += __shfl_xor_sync(0xffffffffu, lap,  s);
        phis += __shfl_xor_sync(0xffffffffu, phis, s);
    }
    if ((tid & 31) == 0) wred[tid >> 5] = make_float4(gx, gy, lap, phis);
    __syncthreads();

    if (tid == 0) {
        float4 tot = wred[0];
        #pragma unroll
        for (int w = 1; w < 8; w++) {
            float4 a = wred[w];
            tot.x += a.x; tot.y += a.y; tot.z += a.z; tot.w += a.w;
        }
        double contrib = 0.0;
        if (deriv) {
            float dtl = t[l + 1] - t[l];
            float dgx = fmaf(-VK, xi.x, -tot.x / NN);
            float dgy = fmaf(-VK, xi.y, -tot.y / NN);
            contrib += (double)dtl * ((double)dgx * dgx + (double)dgy * dgy) / NN;
            contrib += SIG2 * (double)dtl * ((double)tot.z / NN) / NN;
        }
        if (needphi) {
            double sign = (l == 0) ? 2.0 : -2.0;
            contrib += sign * ((double)tot.w / ((double)NN * NN)
                             + 0.5 * (double)VK * ((double)xi.x * xi.x + (double)xi.y * xi.y) / NN);
        }
        atomicAdd(&g_slots[b & 63], contrib);
        __threadfence();
        unsigned old = atomicAdd(&g_cnt, 1u);
        is_last = (old == (unsigned)(NBLK - 1)) ? 1u : 0u;
    }
    __syncthreads();

    if (is_last) {
        __threadfence();
        if (tid < 64) sdbl[tid] = *((volatile double*)&g_slots[tid]);
        __syncthreads();
        if (tid == 0) {
            double S = 0.0;
            #pragma unroll
            for (int k = 0; k < 64; k++) S += sdbl[k];
            S += (double)MM * SIG2 * (double)VK * DDIM * (double)(t[LL - 1] - t[0]);
            double res = S / (double)(MM * (LL - 1));
            out[0] = (float)(res * res);
        }
    }
}

extern "C" void kernel_launch(void* const* d_in, const int* in_sizes, int n_in,
                              void* d_out, int out_size)
{
    const float* data = (const float*)d_in[0];
    const float* t    = (const float*)d_in[1];
    const float* w1   = (const float*)d_in[2];
    const float* b1   = (const float*)d_in[3];
    const float* W2   = (const float*)d_in[4];
    const float* b2   = (const float*)d_in[5];
    const float* w3   = (const float*)d_in[6];
    const float* b3   = (const float*)d_in[7];

    build_table<<<NT * 2 / 128, 128>>>(w1, b1, W2, b2, w3, b3);
    pair_pass<<<NBLK, 256>>>(data, t, (float*)d_out);
}

// round 8
// speedup vs baseline: 48.2964x; 1.4389x over previous
#include <cuda_runtime.h>
#include <cstdint>

#define MM 2
#define LL 6
#define NN 512
#define HH 64
#define VK 1.0f
#define SIG2 0.01
#define DDIM 2.0
#define NT 8192
#define RMAX 16.0f
#define HSTEP (RMAX / (float)NT)
#define NWARP (MM * LL * NN)      // 6144 i-warps total

typedef unsigned long long u64;

__device__ float4 g_raw[NT + 64];   // (phi+b3, dphi, d2phi, 0) at nodes 0..NT
__device__ float4 g_tab[NT];        // (phi, dphi, d2, d2-slope) Taylor entries
__device__ double g_slots[64];
__device__ unsigned g_cnt;

__device__ __forceinline__ float tanh_fast(float x) {
    float y; asm("tanh.approx.f32 %0, %1;" : "=f"(y) : "f"(x)); return y;
}
__device__ __forceinline__ u64 pack2(float x) {
    u64 r; asm("mov.b64 %0, {%1,%1};" : "=l"(r) : "f"(x)); return r;
}
__device__ __forceinline__ u64 pack2f(float lo, float hi) {
    u64 r; asm("mov.b64 %0, {%1,%2};" : "=l"(r) : "f"(lo), "f"(hi)); return r;
}
__device__ __forceinline__ void unpack2(u64 v, float& lo, float& hi) {
    asm("mov.b64 {%0,%1}, %2;" : "=f"(lo), "=f"(hi) : "l"(v));
}
__device__ __forceinline__ u64 fma2(u64 a, u64 b, u64 c) {
    u64 d; asm("fma.rn.f32x2 %0, %1, %2, %3;" : "=l"(d) : "l"(a), "l"(b), "l"(c)); return d;
}

// ---------------- builder: 2 lanes per node (each 32 of 64 channels) ----------------
__global__ void __launch_bounds__(128)
build_table(const float* __restrict__ w1, const float* __restrict__ b1,
            const float* __restrict__ W2, const float* __restrict__ b2,
            const float* __restrict__ w3, const float* __restrict__ b3p)
{
    __shared__ float sW2[HH * HH];
    __shared__ float sw1[HH], sb1[HH], sb2[HH], sw3[HH];
    __shared__ float h1s[HH * 64];

    int tid = threadIdx.x;
    #pragma unroll
    for (int s = 0; s < HH * HH; s += 128) sW2[s + tid] = W2[s + tid];
    if (tid < HH) { sw1[tid] = w1[tid]; sb1[tid] = b1[tid]; sb2[tid] = b2[tid]; sw3[tid] = w3[tid]; }

    if (blockIdx.x == 0) {
        if (tid < 64) g_slots[tid] = 0.0;
        if (tid == 64) g_cnt = 0u;
    }
    __syncthreads();

    int gt   = blockIdx.x * 128 + tid;
    int ridx = gt >> 1;                // node 0..NT (+spill, guarded at write)
    int half = gt & 1;
    int pair = tid >> 1;
    float r = (float)ridx * HSTEP;

    int kbase = half * 32;
    #pragma unroll 8
    for (int k = kbase; k < kbase + 32; k++)
        h1s[k * 64 + pair] = tanh_fast(fmaf(r, sw1[k], sb1[k]));
    __syncthreads();

    float phi = 0.f, dphi = 0.f, d2phi = 0.f;

    #pragma unroll
    for (int cc = 0; cc < 2; cc++) {
        int c = half * 32 + cc * 16;
        u64 z2[8], zp[8], zpp[8];
        #pragma unroll
        for (int p = 0; p < 8; p++) {
            z2[p]  = pack2f(sb2[c + 2 * p], sb2[c + 2 * p + 1]);
            zp[p]  = 0ull;
            zpp[p] = 0ull;
        }
        #pragma unroll 4
        for (int k = 0; k < HH; k++) {
            float h   = h1s[k * 64 + pair];
            float w1k = sw1[k];
            float s   = fmaf(-h, h, 1.f);
            float hp  = s * w1k;
            float hpp = -2.f * h * hp * w1k;
            u64 hh   = pack2(h);
            u64 hpx  = pack2(hp);
            u64 hppx = pack2(hpp);
            const ulonglong2* wr = (const ulonglong2*)(sW2 + k * HH + c);
            #pragma unroll
            for (int q = 0; q < 4; q++) {
                ulonglong2 w = wr[q];
                z2[2 * q]      = fma2(w.x, hh,   z2[2 * q]);
                z2[2 * q + 1]  = fma2(w.y, hh,   z2[2 * q + 1]);
                zp[2 * q]      = fma2(w.x, hpx,  zp[2 * q]);
                zp[2 * q + 1]  = fma2(w.y, hpx,  zp[2 * q + 1]);
                zpp[2 * q]     = fma2(w.x, hppx, zpp[2 * q]);
                zpp[2 * q + 1] = fma2(w.y, hppx, zpp[2 * q + 1]);
            }
        }
        #pragma unroll
        for (int p = 0; p < 8; p++) {
            float a0, a1, p0, p1, q0, q1;
            unpack2(z2[p], a0, a1);
            unpack2(zp[p], p0, p1);
            unpack2(zpp[p], q0, q1);
            float w30 = sw3[c + 2 * p], w31 = sw3[c + 2 * p + 1];

            float h2 = tanh_fast(a0);
            phi = fmaf(w30, h2, phi);
            float e   = fmaf(-h2, h2, 1.f);
            float hp2 = e * p0;
            float hq2 = fmaf(e, q0, -2.f * h2 * hp2 * p0);
            dphi  = fmaf(w30, hp2, dphi);
            d2phi = fmaf(w30, hq2, d2phi);

            h2 = tanh_fast(a1);
            phi = fmaf(w31, h2, phi);
            e   = fmaf(-h2, h2, 1.f);
            hp2 = e * p1;
            hq2 = fmaf(e, q1, -2.f * h2 * hp2 * p1);
            dphi  = fmaf(w31, hp2, dphi);
            d2phi = fmaf(w31, hq2, d2phi);
        }
    }

    phi   += __shfl_xor_sync(0xffffffffu, phi,   1);
    dphi  += __shfl_xor_sync(0xffffffffu, dphi,  1);
    d2phi += __shfl_xor_sync(0xffffffffu, d2phi, 1);

    if (half == 0 && ridx <= NT)
        g_raw[ridx] = make_float4(phi + b3p[0], dphi, d2phi, 0.f);
}

// ---------------- pack: Taylor entries (phi, dphi, d2, d2_{i+1}-d2_i) ----------------
__global__ void __launch_bounds__(256)
pack_table()
{
    int i = blockIdx.x * 256 + threadIdx.x;
    if (i < NT) {
        float4 a = g_raw[i];
        float4 b = g_raw[i + 1];
        g_tab[i] = make_float4(a.x, a.y, a.z, b.z - a.z);
    }
}

// ---------------- pair pass: one warp per i, fused final reduction ----------------
__global__ void __launch_bounds__(256)
pair_pass(const float* __restrict__ data, const float* __restrict__ t,
          float* __restrict__ out)
{
    __shared__ float2 sx[NN];

    int tid  = threadIdx.x;
    int w    = tid >> 5;
    int lane = tid & 31;
    int sl   = blockIdx.x >> 6;          // 0..11
    int i    = (blockIdx.x & 63) * 8 + w;
    int l    = sl % LL;
    int m    = sl / LL;
    bool deriv   = (l < LL - 1);
    bool needphi = (l == 0 || l == LL - 1);

    const float2* snap = (const float2*)(data + ((size_t)(m * LL + l)) * NN * 2);
    sx[tid]       = snap[tid];
    sx[tid + 256] = snap[tid + 256];
    __syncthreads();

    float2 xi = sx[i];
    float gx = 0.f, gy = 0.f, lap = 0.f, phis = 0.f;
    const float scale = (float)NT / RMAX;

    #pragma unroll 8
    for (int jj = 0; jj < 16; jj++) {
        int j = lane + jj * 32;
        float2 xj = sx[j];
        float dx = xi.x - xj.x, dy = xi.y - xj.y;
        float ssq = dx * dx + dy * dy;
        if (j != i) {
            float inv = rsqrtf(fmaxf(ssq, 1e-20f));
            float r = ssq * inv;
            float u = r * scale;
            int i0 = (int)u;
            i0 = (i0 > NT - 2) ? (NT - 2) : i0;
            float f = u - (float)i0;
            float4 e = __ldg(&g_tab[i0]);
            float x  = f * HSTEP;
            float d2 = fmaf(f, e.w, e.z);
            float dp = fmaf(x, fmaf(0.5f * f, e.w, e.z), e.y);
            float ph = fmaf(x, fmaf(0.5f * x, fmaf(0.33333333f * f, e.w, e.z), e.y), e.x);
            phis += ph;
            lap  += d2;
            float c = dp * inv;
            gx = fmaf(c, dx, gx);
            gy = fmaf(c, dy, gy);
        }
    }

    #pragma unroll
    for (int s = 16; s > 0; s >>= 1) {
        gx   += __shfl_xor_sync(0xffffffffu, gx,   s);
        gy   += __shfl_xor_sync(0xffffffffu, gy,   s);
        lap  += __shfl_xor_sync(0xffffffffu, lap,  s);
        phis += __shfl_xor_sync(0xffffffffu, phis, s);
    }

    unsigned old = 0u;
    if (lane == 0) {
        double contrib = 0.0;
        if (deriv) {
            float dtl = t[l + 1] - t[l];
            float dgx = fmaf(-VK, xi.x, -gx / NN);
            float dgy = fmaf(-VK, xi.y, -gy / NN);
            contrib += (double)dtl * ((double)dgx * dgx + (double)dgy * dgy) / NN;
            contrib += SIG2 * (double)dtl * ((double)lap / NN) / NN;
        }
        if (needphi) {
            double sign = (l == 0) ? 2.0 : -2.0;
            contrib += sign * ((double)phis / ((double)NN * NN)
                             + 0.5 * (double)VK * ((double)xi.x * xi.x + (double)xi.y * xi.y) / NN);
        }
        atomicAdd(&g_slots[i & 63], contrib);
        __threadfence();
        old = atomicAdd(&g_cnt, 1u);
    }
    old = __shfl_sync(0xffffffffu, old, 0);

    if (old == (unsigned)(NWARP - 1)) {
        __threadfence();
        double s = *((volatile double*)&g_slots[lane])
                 + *((volatile double*)&g_slots[lane + 32]);
        #pragma unroll
        for (int k = 16; k > 0; k >>= 1) {
            // shuffle a double via two 32-bit halves
            double other;
            {
                u64 v = __double_as_longlong(s);
                uint32_t lo = (uint32_t)v, hi = (uint32_t)(v >> 32);
                lo = __shfl_xor_sync(0xffffffffu, lo, k);
                hi = __shfl_xor_sync(0xffffffffu, hi, k);
                other = __longlong_as_double(((u64)hi << 32) | lo);
            }
            s += other;
        }
        if (lane == 0) {
            s += (double)MM * SIG2 * (double)VK * DDIM * (double)(t[LL - 1] - t[0]);
            double res = s / (double)(MM * (LL - 1));
            out[0] = (float)(res * res);
        }
    }
}

extern "C" void kernel_launch(void* const* d_in, const int* in_sizes, int n_in,
                              void* d_out, int out_size)
{
    const float* data = (const float*)d_in[0];
    const float* t    = (const float*)d_in[1];
    const float* w1   = (const float*)d_in[2];
    const float* b1   = (const float*)d_in[3];
    const float* W2   = (const float*)d_in[4];
    const float* b2   = (const float*)d_in[5];
    const float* w3   = (const float*)d_in[6];
    const float* b3   = (const float*)d_in[7];

    build_table<<<(2 * (NT + 64)) / 128, 128>>>(w1, b1, W2, b2, w3, b3);
    pack_table<<<NT / 256, 256>>>();
    pair_pass<<<12 * 64, 256>>>(data, t, (float*)d_out);
}